// round 6
// baseline (speedup 1.0000x reference)
#include <cuda_runtime.h>
#include <cuda_fp16.h>
#include <cuda_bf16.h>

#define B_  8
#define Q_  256
#define K_  1024
#define D_  256
#define H_  128
#define DV_ 128

#define RPAD 132          // padded row stride in 4-byte words (33 float4)

// scratch: projected q (dup half2), k (paired half2), raw scores
// g_k2[b][kt][j][h] = (k[b][kt*128+j][h], k[b][kt*128+j+64][h])
__device__ __half2 g_q2[B_ * Q_ * H_];
__device__ __half2 g_k2[B_ * 8 * 64 * H_];
__device__ float   g_sc[B_ * Q_ * K_];

__device__ __forceinline__ __half2 tanh_h2(__half2 x) {
    __half2 y;
    asm("tanh.approx.f16x2 %0, %1;"
        : "=r"(*(unsigned int*)&y) : "r"(*(unsigned int*)&x));
    return y;
}

// ---------------------------------------------------------------------------
// Kernel 1: fused projections, row-split: 256 threads, halves own 8 rows each.
// h = tid&127 is the output column; broadcast smem reads of staged input rows.
// ---------------------------------------------------------------------------
__global__ __launch_bounds__(256) void proj_kernel(
    const float* __restrict__ queries, const float* __restrict__ keys,
    const float* __restrict__ Wq, const float* __restrict__ Wk)
{
    __shared__ float s_in[16 * D_];   // 16KB
    int rb = blockIdx.x * 16;
    bool isQ = rb < B_ * Q_;
    const float* src = isQ ? (queries + rb * D_) : (keys + (rb - B_ * Q_) * D_);
    const float* W   = isQ ? Wq : Wk;

    int tid = threadIdx.x;
    int h  = tid & 127;
    int r0 = (tid >> 7) * 8;          // 0 or 8

    const float4* s4 = (const float4*)src;
    float4* d4 = (float4*)s_in;
    #pragma unroll
    for (int i = 0; i < 4; i++) d4[tid + 256 * i] = s4[tid + 256 * i];
    __syncthreads();

    float acc[8];
    #pragma unroll
    for (int r = 0; r < 8; r++) acc[r] = 0.f;

    #pragma unroll 4
    for (int d = 0; d < D_; d += 4) {
        float w0 = W[(d + 0) * H_ + h];
        float w1 = W[(d + 1) * H_ + h];
        float w2 = W[(d + 2) * H_ + h];
        float w3 = W[(d + 3) * H_ + h];
        #pragma unroll
        for (int r = 0; r < 8; r++) {
            float4 a = *(const float4*)&s_in[(r0 + r) * D_ + d];
            acc[r] += a.x * w0 + a.y * w1 + a.z * w2 + a.w * w3;
        }
    }

    if (isQ) {
        #pragma unroll
        for (int r = 0; r < 8; r++) {
            __half v = __float2half(acc[r]);
            g_q2[(rb + r0 + r) * H_ + h] = __halves2half2(v, v);
        }
    } else {
        int rk0 = rb - B_ * Q_ + r0;
        #pragma unroll
        for (int r = 0; r < 8; r++) {
            int rk  = rk0 + r;
            int b   = rk >> 10;
            int rbi = rk & 1023;
            int kt  = rbi >> 7;
            int jj  = rbi & 127;
            int j    = jj & 63;
            int slot = jj >> 6;
            ((__half*)g_k2)[((((b * 8 + kt) * 64 + j) * H_) + h) * 2 + slot] =
                __float2half(acc[r]);
        }
    }
}

// ---------------------------------------------------------------------------
// Kernel 2: scores only. grid (Q/8, K/128, B), 256 threads.
// Block computes an 8q x 128k score tile. Thread: qg = tid>>6 owns q rows
// (2qg, 2qg+1); j = tid&63 owns k pair (j, j+64). HFMA2 accumulation with
// fp32 flush every 8 h-terms.
// ---------------------------------------------------------------------------
__global__ __launch_bounds__(256) void scores_kernel(const float* __restrict__ w_v)
{
    __shared__ float ksw[64 * RPAD];   // k tile, paired half2 (~33.8KB)
    __shared__ float qsw[8 * RPAD];    // q tile, dup half2
    __shared__ float wvs[RPAD];        // w_v as dup half2 (128 words used)

    int b  = blockIdx.z;
    int kt = blockIdx.y;
    int q0 = blockIdx.x * 8;
    int tid = threadIdx.x;

    const float4* srck = (const float4*)(g_k2 + (b * 8 + kt) * 64 * H_);
    #pragma unroll
    for (int l = 0; l < 8; l++) {
        int i = tid + 256 * l;
        int r = i >> 5, c = i & 31;
        *(float4*)(ksw + r * RPAD + c * 4) = srck[i];
    }
    {
        int r = tid >> 5, c = tid & 31;   // 8 rows x 32 float4
        *(float4*)(qsw + r * RPAD + c * 4) =
            ((const float4*)(g_q2 + (b * Q_ + q0 + r) * H_))[c];
    }
    if (tid < 128) {
        __half v = __float2half(w_v[tid]);
        ((__half2*)wvs)[tid] = __halves2half2(v, v);
    }
    __syncthreads();

    int qg = tid >> 6;
    int j  = tid & 63;
    const float4* qa4 = (const float4*)(qsw + (qg * 2    ) * RPAD);
    const float4* qb4 = (const float4*)(qsw + (qg * 2 + 1) * RPAD);
    const float4* kp4 = (const float4*)(ksw + j * RPAD);
    const float4* wv4 = (const float4*)wvs;

    float S00 = 0.f, S01 = 0.f, S10 = 0.f, S11 = 0.f;
    #pragma unroll 4
    for (int hh = 0; hh < 16; hh++) {
        __half2 sa = __float2half2_rn(0.f);
        __half2 sb = __float2half2_rn(0.f);
        #pragma unroll
        for (int t = 0; t < 2; t++) {
            int h4 = hh * 2 + t;
            float4 kv = kp4[h4];
            float4 qa = qa4[h4];
            float4 qb = qb4[h4];
            float4 wf = wv4[h4];
            const __half2* kh  = (const __half2*)&kv;
            const __half2* qah = (const __half2*)&qa;
            const __half2* qbh = (const __half2*)&qb;
            const __half2* wh  = (const __half2*)&wf;
            #pragma unroll
            for (int u = 0; u < 4; u++) {
                __half2 ta = tanh_h2(__hadd2(qah[u], kh[u]));
                __half2 tb = tanh_h2(__hadd2(qbh[u], kh[u]));
                sa = __hfma2(wh[u], ta, sa);
                sb = __hfma2(wh[u], tb, sb);
            }
        }
        float2 fa = __half22float2(sa);
        float2 fb = __half22float2(sb);
        S00 += fa.x; S01 += fa.y;
        S10 += fb.x; S11 += fb.y;
    }

    float* dst = g_sc + (b * Q_ + q0 + qg * 2) * K_ + kt * 128;
    dst[j]           = S00;
    dst[j + 64]      = S01;
    dst[K_ + j]      = S10;
    dst[K_ + j + 64] = S11;
}

// ---------------------------------------------------------------------------
// Kernel 3: masked softmax (from g_sc) + attn @ values.
// grid (Q/8, B), 256 threads. Warp w = q-row w of the 8-row tile.
// ---------------------------------------------------------------------------
__global__ __launch_bounds__(256) void smax_av_kernel(
    const float* __restrict__ values, const int* __restrict__ valid_lens,
    float* __restrict__ out)
{
    __shared__ float sc[8 * K_];   // 32KB, reused for the slice reduction

    int b  = blockIdx.y;
    int q0 = blockIdx.x * 8;
    int tid = threadIdx.x;
    int wid = tid >> 5, lane = tid & 31;
    int vlen = valid_lens[b];

    {
        const float* row = g_sc + (b * Q_ + q0 + wid) * K_;
        float v[32];
        float m = -3e38f;
        #pragma unroll
        for (int jj = 0; jj < 32; jj++) {
            int k = lane + 32 * jj;
            float s = (k < vlen) ? row[k] : -1e6f;
            v[jj] = s;
            m = fmaxf(m, s);
        }
        #pragma unroll
        for (int off = 16; off; off >>= 1)
            m = fmaxf(m, __shfl_xor_sync(0xffffffffu, m, off));
        float sum = 0.f;
        #pragma unroll
        for (int jj = 0; jj < 32; jj++) { v[jj] = __expf(v[jj] - m); sum += v[jj]; }
        #pragma unroll
        for (int off = 16; off; off >>= 1)
            sum += __shfl_xor_sync(0xffffffffu, sum, off);
        float inv = 1.f / sum;
        #pragma unroll
        for (int jj = 0; jj < 32; jj++)
            sc[wid * K_ + lane + 32 * jj] = v[jj] * inv;
    }
    __syncthreads();

    int v4 = tid & 31;
    int slice = tid >> 5;
    float4 acc[8];
    #pragma unroll
    for (int r = 0; r < 8; r++) acc[r] = make_float4(0.f, 0.f, 0.f, 0.f);
    const float4* vb = (const float4*)(values + b * K_ * DV_);
    #pragma unroll 4
    for (int k = slice; k < K_; k += 8) {
        float4 vv = vb[k * 32 + v4];
        #pragma unroll
        for (int r = 0; r < 8; r++) {
            float a = sc[r * K_ + k];
            acc[r].x += a * vv.x; acc[r].y += a * vv.y;
            acc[r].z += a * vv.z; acc[r].w += a * vv.w;
        }
    }
    __syncthreads();
    float4* red = (float4*)sc;
    #pragma unroll
    for (int r = 0; r < 8; r++) red[(slice * 8 + r) * 32 + v4] = acc[r];
    __syncthreads();
    {
        int r = tid >> 5, c = tid & 31;
        float4 o = make_float4(0.f, 0.f, 0.f, 0.f);
        #pragma unroll
        for (int s = 0; s < 8; s++) {
            float4 t = red[(s * 8 + r) * 32 + c];
            o.x += t.x; o.y += t.y; o.z += t.z; o.w += t.w;
        }
        ((float4*)(out + (b * Q_ + q0 + r) * DV_))[c] = o;
    }
}

extern "C" void kernel_launch(void* const* d_in, const int* in_sizes, int n_in,
                              void* d_out, int out_size)
{
    const float* queries    = (const float*)d_in[0];
    const float* keys       = (const float*)d_in[1];
    const float* values     = (const float*)d_in[2];
    const int*   valid_lens = (const int*)  d_in[3];
    const float* W_q        = (const float*)d_in[4];
    const float* W_k        = (const float*)d_in[5];
    const float* w_v        = (const float*)d_in[6];
    float* out = (float*)d_out;

    proj_kernel<<<(B_ * Q_ + B_ * K_) / 16, 256>>>(queries, keys, W_q, W_k);
    scores_kernel<<<dim3(Q_ / 8, K_ / 128, B_), 256>>>(w_v);
    smax_av_kernel<<<dim3(Q_ / 8, B_), 256>>>(values, valid_lens, out);
}

// round 7
// speedup vs baseline: 1.0411x; 1.0411x over previous
#include <cuda_runtime.h>
#include <cuda_fp16.h>
#include <cuda_bf16.h>

#define B_  8
#define Q_  256
#define K_  1024
#define D_  256
#define H_  128
#define DV_ 128

#define RPAD 132          // padded row stride in 4-byte words (33 float4)

// scratch: projected q (dup half2), k (paired half2), raw scores
// g_k2[b][kt][j][h] = (k[b][kt*128+j][h], k[b][kt*128+j+64][h])
__device__ __half2 g_q2[B_ * Q_ * H_];
__device__ __half2 g_k2[B_ * 8 * 64 * H_];
__device__ float   g_sc[B_ * Q_ * K_];

__device__ __forceinline__ __half2 tanh_h2(__half2 x) {
    __half2 y;
    asm("tanh.approx.f16x2 %0, %1;"
        : "=r"(*(unsigned int*)&y) : "r"(*(unsigned int*)&x));
    return y;
}

// ---------------------------------------------------------------------------
// Kernel 1: fused projections. 128 threads, 16 rows per block.
// Thread t: c4 = t&31 owns h columns 4c4..4c4+3 (float4 of W row),
//           rg = t>>5 owns rows 4rg..4rg+3.
// Per 4 d: 4x LDG.128 (W, warp-coalesced, L1-resident) + 4x broadcast
// LDS.128 (staged inputs) + 64 FFMA.
// ---------------------------------------------------------------------------
__global__ __launch_bounds__(128) void proj_kernel(
    const float* __restrict__ queries, const float* __restrict__ keys,
    const float* __restrict__ Wq, const float* __restrict__ Wk)
{
    __shared__ float s_in[16 * D_];   // 16KB
    int rb = blockIdx.x * 16;
    bool isQ = rb < B_ * Q_;
    const float* src = isQ ? (queries + rb * D_) : (keys + (rb - B_ * Q_) * D_);
    const float* W   = isQ ? Wq : Wk;

    int tid = threadIdx.x;
    int c4 = tid & 31;          // float4 column of W / output h-group
    int rg = tid >> 5;          // 0..3 -> rows 4rg..4rg+3

    // stage 16 input rows (16KB contiguous)
    const float4* s4 = (const float4*)src;
    float4* d4 = (float4*)s_in;
    #pragma unroll
    for (int i = 0; i < 8; i++) d4[tid + 128 * i] = s4[tid + 128 * i];
    __syncthreads();

    float4 acc[4];
    #pragma unroll
    for (int r = 0; r < 4; r++) acc[r] = make_float4(0.f, 0.f, 0.f, 0.f);

    const float4* Wp = (const float4*)W;   // row d = 32 float4
    #pragma unroll 4
    for (int d = 0; d < D_; d += 4) {
        float4 w0 = Wp[(d + 0) * 32 + c4];
        float4 w1 = Wp[(d + 1) * 32 + c4];
        float4 w2 = Wp[(d + 2) * 32 + c4];
        float4 w3 = Wp[(d + 3) * 32 + c4];
        #pragma unroll
        for (int r = 0; r < 4; r++) {
            float4 a = *(const float4*)&s_in[(rg * 4 + r) * D_ + d];
            acc[r].x += a.x * w0.x + a.y * w1.x + a.z * w2.x + a.w * w3.x;
            acc[r].y += a.x * w0.y + a.y * w1.y + a.z * w2.y + a.w * w3.y;
            acc[r].z += a.x * w0.z + a.y * w1.z + a.z * w2.z + a.w * w3.z;
            acc[r].w += a.x * w0.w + a.y * w1.w + a.z * w2.w + a.w * w3.w;
        }
    }

    if (isQ) {
        #pragma unroll
        for (int r = 0; r < 4; r++) {
            int row = rb + rg * 4 + r;
            __half2 o[4];
            o[0] = __half2half2(__float2half(acc[r].x));
            o[1] = __half2half2(__float2half(acc[r].y));
            o[2] = __half2half2(__float2half(acc[r].z));
            o[3] = __half2half2(__float2half(acc[r].w));
            *(float4*)&g_q2[row * H_ + c4 * 4] = *(float4*)o;
        }
    } else {
        #pragma unroll
        for (int r = 0; r < 4; r++) {
            int rk  = rb - B_ * Q_ + rg * 4 + r;
            int b   = rk >> 10;
            int rbi = rk & 1023;
            int kt  = rbi >> 7;
            int jj  = rbi & 127;
            int j    = jj & 63;
            int slot = jj >> 6;
            __half* base = (__half*)g_k2 + (((b * 8 + kt) * 64 + j) * H_) * 2 + slot;
            base[(c4 * 4 + 0) * 2] = __float2half(acc[r].x);
            base[(c4 * 4 + 1) * 2] = __float2half(acc[r].y);
            base[(c4 * 4 + 2) * 2] = __float2half(acc[r].z);
            base[(c4 * 4 + 3) * 2] = __float2half(acc[r].w);
        }
    }
}

// ---------------------------------------------------------------------------
// Kernel 2: scores only (UNCHANGED). grid (Q/8, K/128, B), 256 threads.
// ---------------------------------------------------------------------------
__global__ __launch_bounds__(256) void scores_kernel(const float* __restrict__ w_v)
{
    __shared__ float ksw[64 * RPAD];
    __shared__ float qsw[8 * RPAD];
    __shared__ float wvs[RPAD];

    int b  = blockIdx.z;
    int kt = blockIdx.y;
    int q0 = blockIdx.x * 8;
    int tid = threadIdx.x;

    const float4* srck = (const float4*)(g_k2 + (b * 8 + kt) * 64 * H_);
    #pragma unroll
    for (int l = 0; l < 8; l++) {
        int i = tid + 256 * l;
        int r = i >> 5, c = i & 31;
        *(float4*)(ksw + r * RPAD + c * 4) = srck[i];
    }
    {
        int r = tid >> 5, c = tid & 31;
        *(float4*)(qsw + r * RPAD + c * 4) =
            ((const float4*)(g_q2 + (b * Q_ + q0 + r) * H_))[c];
    }
    if (tid < 128) {
        __half v = __float2half(w_v[tid]);
        ((__half2*)wvs)[tid] = __halves2half2(v, v);
    }
    __syncthreads();

    int qg = tid >> 6;
    int j  = tid & 63;
    const float4* qa4 = (const float4*)(qsw + (qg * 2    ) * RPAD);
    const float4* qb4 = (const float4*)(qsw + (qg * 2 + 1) * RPAD);
    const float4* kp4 = (const float4*)(ksw + j * RPAD);
    const float4* wv4 = (const float4*)wvs;

    float S00 = 0.f, S01 = 0.f, S10 = 0.f, S11 = 0.f;
    #pragma unroll 4
    for (int hh = 0; hh < 16; hh++) {
        __half2 sa = __float2half2_rn(0.f);
        __half2 sb = __float2half2_rn(0.f);
        #pragma unroll
        for (int t = 0; t < 2; t++) {
            int h4 = hh * 2 + t;
            float4 kv = kp4[h4];
            float4 qa = qa4[h4];
            float4 qb = qb4[h4];
            float4 wf = wv4[h4];
            const __half2* kh  = (const __half2*)&kv;
            const __half2* qah = (const __half2*)&qa;
            const __half2* qbh = (const __half2*)&qb;
            const __half2* wh  = (const __half2*)&wf;
            #pragma unroll
            for (int u = 0; u < 4; u++) {
                __half2 ta = tanh_h2(__hadd2(qah[u], kh[u]));
                __half2 tb = tanh_h2(__hadd2(qbh[u], kh[u]));
                sa = __hfma2(wh[u], ta, sa);
                sb = __hfma2(wh[u], tb, sb);
            }
        }
        float2 fa = __half22float2(sa);
        float2 fb = __half22float2(sb);
        S00 += fa.x; S01 += fa.y;
        S10 += fb.x; S11 += fb.y;
    }

    float* dst = g_sc + (b * Q_ + q0 + qg * 2) * K_ + kt * 128;
    dst[j]           = S00;
    dst[j + 64]      = S01;
    dst[K_ + j]      = S10;
    dst[K_ + j + 64] = S11;
}

// ---------------------------------------------------------------------------
// Kernel 3: masked softmax + attn @ values (UNCHANGED). grid (Q/8, B).
// ---------------------------------------------------------------------------
__global__ __launch_bounds__(256) void smax_av_kernel(
    const float* __restrict__ values, const int* __restrict__ valid_lens,
    float* __restrict__ out)
{
    __shared__ float sc[8 * K_];

    int b  = blockIdx.y;
    int q0 = blockIdx.x * 8;
    int tid = threadIdx.x;
    int wid = tid >> 5, lane = tid & 31;
    int vlen = valid_lens[b];

    {
        const float* row = g_sc + (b * Q_ + q0 + wid) * K_;
        float v[32];
        float m = -3e38f;
        #pragma unroll
        for (int jj = 0; jj < 32; jj++) {
            int k = lane + 32 * jj;
            float s = (k < vlen) ? row[k] : -1e6f;
            v[jj] = s;
            m = fmaxf(m, s);
        }
        #pragma unroll
        for (int off = 16; off; off >>= 1)
            m = fmaxf(m, __shfl_xor_sync(0xffffffffu, m, off));
        float sum = 0.f;
        #pragma unroll
        for (int jj = 0; jj < 32; jj++) { v[jj] = __expf(v[jj] - m); sum += v[jj]; }
        #pragma unroll
        for (int off = 16; off; off >>= 1)
            sum += __shfl_xor_sync(0xffffffffu, sum, off);
        float inv = 1.f / sum;
        #pragma unroll
        for (int jj = 0; jj < 32; jj++)
            sc[wid * K_ + lane + 32 * jj] = v[jj] * inv;
    }
    __syncthreads();

    int v4 = tid & 31;
    int slice = tid >> 5;
    float4 acc[8];
    #pragma unroll
    for (int r = 0; r < 8; r++) acc[r] = make_float4(0.f, 0.f, 0.f, 0.f);
    const float4* vb = (const float4*)(values + b * K_ * DV_);
    #pragma unroll 4
    for (int k = slice; k < K_; k += 8) {
        float4 vv = vb[k * 32 + v4];
        #pragma unroll
        for (int r = 0; r < 8; r++) {
            float a = sc[r * K_ + k];
            acc[r].x += a * vv.x; acc[r].y += a * vv.y;
            acc[r].z += a * vv.z; acc[r].w += a * vv.w;
        }
    }
    __syncthreads();
    float4* red = (float4*)sc;
    #pragma unroll
    for (int r = 0; r < 8; r++) red[(slice * 8 + r) * 32 + v4] = acc[r];
    __syncthreads();
    {
        int r = tid >> 5, c = tid & 31;
        float4 o = make_float4(0.f, 0.f, 0.f, 0.f);
        #pragma unroll
        for (int s = 0; s < 8; s++) {
            float4 t = red[(s * 8 + r) * 32 + c];
            o.x += t.x; o.y += t.y; o.z += t.z; o.w += t.w;
        }
        ((float4*)(out + (b * Q_ + q0 + r) * DV_))[c] = o;
    }
}

extern "C" void kernel_launch(void* const* d_in, const int* in_sizes, int n_in,
                              void* d_out, int out_size)
{
    const float* queries    = (const float*)d_in[0];
    const float* keys       = (const float*)d_in[1];
    const float* values     = (const float*)d_in[2];
    const int*   valid_lens = (const int*)  d_in[3];
    const float* W_q        = (const float*)d_in[4];
    const float* W_k        = (const float*)d_in[5];
    const float* w_v        = (const float*)d_in[6];
    float* out = (float*)d_out;

    proj_kernel<<<(B_ * Q_ + B_ * K_) / 16, 128>>>(queries, keys, W_q, W_k);
    scores_kernel<<<dim3(Q_ / 8, K_ / 128, B_), 256>>>(w_v);
    smax_av_kernel<<<dim3(Q_ / 8, B_), 256>>>(values, valid_lens, out);
}